// round 8
// baseline (speedup 1.0000x reference)
#include <cuda_runtime.h>

// ---------------------------------------------------------------------------
// DFMNET: 2-layer LSTM (B=2048, T=256, I=64, H=128) + 6-layer MLP head.
// Persistent CTA per 16 batch rows runs all 256 timesteps.
// R8: L1-return-bandwidth fix. Thread = 8 gate cols x 8 rows over K/4
// (4-way split-K, 512 threads). Per 2-k chunk/warp: 64 FFMA2 vs 2KB LDS +
// 2KB LDG return -> FMA pipe is the binder (broadcast LDS.128 costs 4 return
// wavefronts; R6's 16-rows-per-thread made L1 return 2.1x FMA).
// Weights fp32 [chunk][64 col-strips][16] -> 4 coalesced LDG.128 per chunk,
// depth-1 double-buffered with padded tail. fp32 f32x2 math throughout.
// ---------------------------------------------------------------------------

#define T_SEQ    256
#define I_IN     64
#define H_HID    128
#define ROWS     16            // batch rows per CTA
#define NTHREADS 512
#define KROWS    320           // xh rows: [x(64) | h1(128) | h2(128)]
#define GSTR     516           // gate-buffer row stride (floats)
#define BSTR     (ROWS * GSTR) // per-partial-buffer stride (floats)

typedef unsigned long long ull;

// Weights: [chunk][cs=0..63][16 floats] where the 16 floats are
// (c0k0,c0k1, c1k0,c1k1, ..., c7k0,c7k1) for cols cs*8..cs*8+7, k=2c,2c+1.
// +1 zero-padded chunk so the depth-1 prefetch never branches.
__device__ __align__(16) float g_Wt1[(96 + 1) * 1024];    // K=192 -> 96 chunks
__device__ __align__(16) float g_Wt2[(128 + 1) * 1024];   // K=256 -> 128 chunks
__device__ float g_b1[512];
__device__ float g_b2[512];

// ---- packed fp32x2 helpers ----
__device__ __forceinline__ ull fma2(ull a, ull b, ull c) {
    ull d;
    asm("fma.rn.f32x2 %0, %1, %2, %3;" : "=l"(d) : "l"(a), "l"(b), "l"(c));
    return d;
}
__device__ __forceinline__ void unpack2(ull v, float& lo, float& hi) {
    unsigned a, b;
    asm("mov.b64 {%0, %1}, %2;" : "=r"(a), "=r"(b) : "l"(v));
    lo = __uint_as_float(a); hi = __uint_as_float(b);
}
__device__ __forceinline__ ull dup2(float w) {
    ull r; unsigned u = __float_as_uint(w);
    asm("mov.b64 %0, {%1, %1};" : "=l"(r) : "r"(u));
    return r;
}

__device__ __forceinline__ float sigf(float v) {
    return __fdividef(1.f, 1.f + __expf(-v));
}
__device__ __forceinline__ float tanhf_fast(float v) {
    float z = fminf(fmaxf(v, -15.f), 15.f);
    float e = __expf(-2.f * z);
    return __fdividef(1.f - e, 1.f + e);
}

// ---------------------------------------------------------------------------
// Weight repack into [chunk][cs][ci*2+s] layout described above.
// ---------------------------------------------------------------------------
__global__ void prep_kernel(const float* __restrict__ Wih1, const float* __restrict__ Whh1,
                            const float* __restrict__ bih1, const float* __restrict__ bhh1,
                            const float* __restrict__ Wih2, const float* __restrict__ Whh2,
                            const float* __restrict__ bih2, const float* __restrict__ bhh2)
{
    int tid = blockIdx.x * blockDim.x + threadIdx.x;
    int stride = gridDim.x * blockDim.x;
    if (tid < 512) {
        g_b1[tid] = bih1[tid] + bhh1[tid];
        g_b2[tid] = bih2[tid] + bhh2[tid];
    }
    for (int e = tid; e < 97 * 1024; e += stride) {
        int c = e >> 10, r = e & 1023;
        int cs = r >> 4, q = r & 15, ci = q >> 1, s = q & 1;
        int g = cs * 8 + ci;
        int k = 2 * c + s;
        float w = 0.f;
        if (k < 192) w = (k < 64) ? Wih1[g * 64 + k] : Whh1[g * 128 + (k - 64)];
        g_Wt1[e] = w;
    }
    for (int e = tid; e < 129 * 1024; e += stride) {
        int c = e >> 10, r = e & 1023;
        int cs = r >> 4, q = r & 15, ci = q >> 1, s = q & 1;
        int g = cs * 8 + ci;
        int k = 2 * c + s;
        float w = 0.f;
        if (k < 256) w = (k < 128) ? Wih2[g * 128 + k] : Whh2[g * 128 + (k - 128)];
        g_Wt2[e] = w;
    }
}

// ---------------------------------------------------------------------------
// Partial gate GEMM over chunk range [cb, cb+nc):
//   gbuf[16][GSTR] = (bias?) + xh-slice @ Wt-slice for this thread's
//   8 cols (cs*8..cs*8+7) x 8 rows (rg*8..rg*8+7).
// acc[ci][rp] = f32x2 over rows (rg*8+2rp, rg*8+2rp+1), col cs*8+ci.
// Per chunk: 4 LDG.128 (prefetch, coalesced), 4 broadcast LDS.128, 16 dup
// MOVs, 64 FFMA2.
// ---------------------------------------------------------------------------
__device__ __forceinline__ void gemm_gates(const float* __restrict__ Wt,
                                           const float* __restrict__ bias,
                                           const float* __restrict__ xh,   // [k][16]
                                           float* __restrict__ gbuf,       // [16][GSTR]
                                           int cb, int nc, int rg, int cs, bool add_bias)
{
    const int c0 = cs * 8;
    ull acc[8][4];
    if (add_bias) {
#pragma unroll
        for (int ci = 0; ci < 8; ci++) {
            ull b = dup2(bias[c0 + ci]);
#pragma unroll
            for (int rp = 0; rp < 4; rp++) acc[ci][rp] = b;
        }
    } else {
#pragma unroll
        for (int ci = 0; ci < 8; ci++)
#pragma unroll
            for (int rp = 0; rp < 4; rp++) acc[ci][rp] = 0ull;
    }

    const float4* Wp = (const float4*)(Wt + (cb * 64 + cs) * 16);  // 4 float4/thread/chunk
    float4 w0 = Wp[0], w1 = Wp[1], w2 = Wp[2], w3 = Wp[3];
    const ulonglong2* xq = (const ulonglong2*)(xh + cb * 32 + rg * 8);

#pragma unroll 4
    for (int c = 0; c < nc; c++) {
        // prefetch next chunk's weights (padded tail: always safe)
        float4 n0 = Wp[256], n1 = Wp[257], n2 = Wp[258], n3 = Wp[259];
        Wp += 256;
        // this thread's 8 rows for k=2c (q0,q1) and k=2c+1 (q2,q3); broadcast
        ulonglong2 q0 = xq[0], q1 = xq[1];
        ulonglong2 q2 = xq[4], q3 = xq[5];
        xq += 8;

        ull t;
        // ci=0
        t = dup2(w0.x);
        acc[0][0] = fma2(t, q0.x, acc[0][0]); acc[0][1] = fma2(t, q0.y, acc[0][1]);
        acc[0][2] = fma2(t, q1.x, acc[0][2]); acc[0][3] = fma2(t, q1.y, acc[0][3]);
        t = dup2(w0.y);
        acc[0][0] = fma2(t, q2.x, acc[0][0]); acc[0][1] = fma2(t, q2.y, acc[0][1]);
        acc[0][2] = fma2(t, q3.x, acc[0][2]); acc[0][3] = fma2(t, q3.y, acc[0][3]);
        // ci=1
        t = dup2(w0.z);
        acc[1][0] = fma2(t, q0.x, acc[1][0]); acc[1][1] = fma2(t, q0.y, acc[1][1]);
        acc[1][2] = fma2(t, q1.x, acc[1][2]); acc[1][3] = fma2(t, q1.y, acc[1][3]);
        t = dup2(w0.w);
        acc[1][0] = fma2(t, q2.x, acc[1][0]); acc[1][1] = fma2(t, q2.y, acc[1][1]);
        acc[1][2] = fma2(t, q3.x, acc[1][2]); acc[1][3] = fma2(t, q3.y, acc[1][3]);
        // ci=2
        t = dup2(w1.x);
        acc[2][0] = fma2(t, q0.x, acc[2][0]); acc[2][1] = fma2(t, q0.y, acc[2][1]);
        acc[2][2] = fma2(t, q1.x, acc[2][2]); acc[2][3] = fma2(t, q1.y, acc[2][3]);
        t = dup2(w1.y);
        acc[2][0] = fma2(t, q2.x, acc[2][0]); acc[2][1] = fma2(t, q2.y, acc[2][1]);
        acc[2][2] = fma2(t, q3.x, acc[2][2]); acc[2][3] = fma2(t, q3.y, acc[2][3]);
        // ci=3
        t = dup2(w1.z);
        acc[3][0] = fma2(t, q0.x, acc[3][0]); acc[3][1] = fma2(t, q0.y, acc[3][1]);
        acc[3][2] = fma2(t, q1.x, acc[3][2]); acc[3][3] = fma2(t, q1.y, acc[3][3]);
        t = dup2(w1.w);
        acc[3][0] = fma2(t, q2.x, acc[3][0]); acc[3][1] = fma2(t, q2.y, acc[3][1]);
        acc[3][2] = fma2(t, q3.x, acc[3][2]); acc[3][3] = fma2(t, q3.y, acc[3][3]);
        // ci=4
        t = dup2(w2.x);
        acc[4][0] = fma2(t, q0.x, acc[4][0]); acc[4][1] = fma2(t, q0.y, acc[4][1]);
        acc[4][2] = fma2(t, q1.x, acc[4][2]); acc[4][3] = fma2(t, q1.y, acc[4][3]);
        t = dup2(w2.y);
        acc[4][0] = fma2(t, q2.x, acc[4][0]); acc[4][1] = fma2(t, q2.y, acc[4][1]);
        acc[4][2] = fma2(t, q3.x, acc[4][2]); acc[4][3] = fma2(t, q3.y, acc[4][3]);
        // ci=5
        t = dup2(w2.z);
        acc[5][0] = fma2(t, q0.x, acc[5][0]); acc[5][1] = fma2(t, q0.y, acc[5][1]);
        acc[5][2] = fma2(t, q1.x, acc[5][2]); acc[5][3] = fma2(t, q1.y, acc[5][3]);
        t = dup2(w2.w);
        acc[5][0] = fma2(t, q2.x, acc[5][0]); acc[5][1] = fma2(t, q2.y, acc[5][1]);
        acc[5][2] = fma2(t, q3.x, acc[5][2]); acc[5][3] = fma2(t, q3.y, acc[5][3]);
        // ci=6
        t = dup2(w3.x);
        acc[6][0] = fma2(t, q0.x, acc[6][0]); acc[6][1] = fma2(t, q0.y, acc[6][1]);
        acc[6][2] = fma2(t, q1.x, acc[6][2]); acc[6][3] = fma2(t, q1.y, acc[6][3]);
        t = dup2(w3.y);
        acc[6][0] = fma2(t, q2.x, acc[6][0]); acc[6][1] = fma2(t, q2.y, acc[6][1]);
        acc[6][2] = fma2(t, q3.x, acc[6][2]); acc[6][3] = fma2(t, q3.y, acc[6][3]);
        // ci=7
        t = dup2(w3.z);
        acc[7][0] = fma2(t, q0.x, acc[7][0]); acc[7][1] = fma2(t, q0.y, acc[7][1]);
        acc[7][2] = fma2(t, q1.x, acc[7][2]); acc[7][3] = fma2(t, q1.y, acc[7][3]);
        t = dup2(w3.w);
        acc[7][0] = fma2(t, q2.x, acc[7][0]); acc[7][1] = fma2(t, q2.y, acc[7][1]);
        acc[7][2] = fma2(t, q3.x, acc[7][2]); acc[7][3] = fma2(t, q3.y, acc[7][3]);

        w0 = n0; w1 = n1; w2 = n2; w3 = n3;
    }

    // write 8 rows x 8 cols: two float4 STS per row
#pragma unroll
    for (int rp = 0; rp < 4; rp++) {
        float la[8], ha[8];
#pragma unroll
        for (int ci = 0; ci < 8; ci++) unpack2(acc[ci][rp], la[ci], ha[ci]);
        int row0 = rg * 8 + 2 * rp;
        float* d0 = gbuf + row0 * GSTR + c0;
        float* d1 = d0 + GSTR;
        *(float4*)(d0)     = make_float4(la[0], la[1], la[2], la[3]);
        *(float4*)(d0 + 4) = make_float4(la[4], la[5], la[6], la[7]);
        *(float4*)(d1)     = make_float4(ha[0], ha[1], ha[2], ha[3]);
        *(float4*)(d1 + 4) = make_float4(ha[4], ha[5], ha[6], ha[7]);
    }
}

// Small MLP layer over the CTA's 16 rows (head only; negligible cost)
__device__ __forceinline__ void mlp_layer(const float* __restrict__ vin, int Din,
                                          const float* __restrict__ W, const float* __restrict__ b,
                                          float* __restrict__ vout, int Dout, bool relu, int tid)
{
    for (int e = tid; e < ROWS * Dout; e += NTHREADS) {
        int r = e / Dout, o = e - r * Dout;
        const float* w = W + o * Din;
        const float* vi = vin + r * Din;
        float s = b[o];
        for (int i = 0; i < Din; i += 4) {
            s += w[i] * vi[i] + w[i + 1] * vi[i + 1] + w[i + 2] * vi[i + 2] + w[i + 3] * vi[i + 3];
        }
        vout[e] = relu ? fmaxf(s, 0.f) : s;
    }
    __syncthreads();
}

// ---------------------------------------------------------------------------
__global__ void __launch_bounds__(NTHREADS, 1)
dfmnet_main(const float* __restrict__ x,
            const float* __restrict__ Wk0, const float* __restrict__ bk0,
            const float* __restrict__ Wk1, const float* __restrict__ bk1,
            const float* __restrict__ Wk2, const float* __restrict__ bk2,
            const float* __restrict__ Wk3, const float* __restrict__ bk3,
            const float* __restrict__ Wk4, const float* __restrict__ bk4,
            const float* __restrict__ Wk5, const float* __restrict__ bk5,
            float* __restrict__ out, int Bn)
{
    extern __shared__ float sm[];
    float* xh    = sm;                    // [KROWS][16]
    float* gates = sm + KROWS * ROWS;     // 4 partial buffers [16][GSTR] each

    const int tid = threadIdx.x;
    const int kg  = tid >> 7;             // k-group 0..3 (4 warps each)
    const int rg  = (tid >> 6) & 1;       // row-group 0/1 (uniform per warp)
    const int cs  = tid & 63;             // col-strip: cols cs*8..cs*8+7
    const int b0  = blockIdx.x * ROWS;

    for (int e = tid; e < KROWS * ROWS; e += NTHREADS) xh[e] = 0.f;
    float c1r[4], c2r[4];
#pragma unroll
    for (int p = 0; p < 4; p++) { c1r[p] = 0.f; c2r[p] = 0.f; }
    __syncthreads();

    const float* xbase = x + (size_t)b0 * T_SEQ * I_IN;
    float* mybuf = gates + kg * BSTR;

    for (int t = 0; t < T_SEQ; t++) {
        // load x_t (16 rows x 64) transposed into xh rows [0,64)
#pragma unroll
        for (int q = 0; q < 2; q++) {
            int e = tid + q * NTHREADS;            // 0..1023
            int r = e >> 6, k = e & 63;
            xh[k * ROWS + r] = xbase[(size_t)r * (T_SEQ * I_IN) + t * I_IN + k];
        }
        __syncthreads();

        // layer 1: K=192 -> 96 chunks, 24 per k-group
        gemm_gates(g_Wt1, g_b1, xh, mybuf, kg * 24, 24, rg, cs, kg == 0);
        __syncthreads();

        // layer 1 activation: h1 -> xh rows [64,192); sum 4 partials
#pragma unroll
        for (int p = 0; p < 4; p++) {
            int idx = tid + p * NTHREADS;          // 0..2047
            int j = idx >> 4, r = idx & 15;
            const float* gb = gates + r * GSTR + j;
            float pi = gb[0]   + gb[BSTR]       + gb[2 * BSTR]       + gb[3 * BSTR];
            float pf = gb[128] + gb[BSTR + 128] + gb[2 * BSTR + 128] + gb[3 * BSTR + 128];
            float pg = gb[256] + gb[BSTR + 256] + gb[2 * BSTR + 256] + gb[3 * BSTR + 256];
            float po = gb[384] + gb[BSTR + 384] + gb[2 * BSTR + 384] + gb[3 * BSTR + 384];
            float iv = sigf(pi);
            float fv = sigf(pf);
            float gv = tanhf_fast(pg);
            float ov = sigf(po);
            float c = fv * c1r[p] + iv * gv;
            c1r[p] = c;
            xh[(64 + j) * ROWS + r] = ov * tanhf_fast(c);
        }
        __syncthreads();

        // layer 2: K=256 -> 128 chunks, 32 per k-group; xh rows [64,320)
        gemm_gates(g_Wt2, g_b2, xh + 64 * ROWS, mybuf, kg * 32, 32, rg, cs, kg == 0);
        __syncthreads();

        // layer 2 activation: h2 -> xh rows [192,320)
#pragma unroll
        for (int p = 0; p < 4; p++) {
            int idx = tid + p * NTHREADS;
            int j = idx >> 4, r = idx & 15;
            const float* gb = gates + r * GSTR + j;
            float pi = gb[0]   + gb[BSTR]       + gb[2 * BSTR]       + gb[3 * BSTR];
            float pf = gb[128] + gb[BSTR + 128] + gb[2 * BSTR + 128] + gb[3 * BSTR + 128];
            float pg = gb[256] + gb[BSTR + 256] + gb[2 * BSTR + 256] + gb[3 * BSTR + 256];
            float po = gb[384] + gb[BSTR + 384] + gb[2 * BSTR + 384] + gb[3 * BSTR + 384];
            float iv = sigf(pi);
            float fv = sigf(pf);
            float gv = tanhf_fast(pg);
            float ov = sigf(po);
            float c = fv * c2r[p] + iv * gv;
            c2r[p] = c;
            xh[(192 + j) * ROWS + r] = ov * tanhf_fast(c);
        }
        // next iter's x-load writes disjoint smem; its __syncthreads orders
        // these h2 writes (and this phase's gates reads) before reuse.
    }
    __syncthreads();

    // ---- outputs: tuple (y, h2, r) flattened ----
    float* out_y  = out;                              // [Bn][64]
    float* out_h2 = out + (size_t)Bn * 64;            // [Bn][128]
    float* out_r  = out + (size_t)Bn * 192;           // [Bn][192]

    float* va = gates;              // [16][192]
    float* vb = gates + ROWS * 192; // [16][128]
    float* vc = vb + ROWS * 128;    // [16][128]
    for (int e = tid; e < ROWS * 192; e += NTHREADS) {
        int r = e / 192, j = e - r * 192;
        float v = (j < 128) ? xh[(192 + j) * ROWS + r] : xh[(j - 128) * ROWS + r];
        va[e] = v;
        out_r[(size_t)(b0 + r) * 192 + j] = v;
        if (j < 128) out_h2[(size_t)(b0 + r) * 128 + j] = v;
    }
    __syncthreads();

    mlp_layer(va, 192, Wk0, bk0, vb, 128, true, tid);
    mlp_layer(vb, 128, Wk1, bk1, vc, 128, true, tid);
    mlp_layer(vc, 128, Wk2, bk2, vb, 128, true, tid);
    mlp_layer(vb, 128, Wk3, bk3, vc, 128, true, tid);
    mlp_layer(vc, 128, Wk4, bk4, vb, 128, true, tid);

    for (int e = tid; e < ROWS * 64; e += NTHREADS) {
        int r = e >> 6, o = e & 63;
        const float* w = Wk5 + o * 128;
        const float* vi = vb + r * 128;
        float s = bk5[o];
        for (int i = 0; i < 128; i += 4) {
            s += w[i] * vi[i] + w[i + 1] * vi[i + 1] + w[i + 2] * vi[i + 2] + w[i + 3] * vi[i + 3];
        }
        out_y[(size_t)(b0 + r) * 64 + o] = s;
    }
}

// ---------------------------------------------------------------------------
extern "C" void kernel_launch(void* const* d_in, const int* in_sizes, int n_in,
                              void* d_out, int out_size)
{
    const float* x    = (const float*)d_in[0];
    const float* Wih1 = (const float*)d_in[1];
    const float* Whh1 = (const float*)d_in[2];
    const float* bih1 = (const float*)d_in[3];
    const float* bhh1 = (const float*)d_in[4];
    const float* Wih2 = (const float*)d_in[5];
    const float* Whh2 = (const float*)d_in[6];
    const float* bih2 = (const float*)d_in[7];
    const float* bhh2 = (const float*)d_in[8];
    const float* Wk0 = (const float*)d_in[9];   const float* bk0 = (const float*)d_in[10];
    const float* Wk1 = (const float*)d_in[11];  const float* bk1 = (const float*)d_in[12];
    const float* Wk2 = (const float*)d_in[13];  const float* bk2 = (const float*)d_in[14];
    const float* Wk3 = (const float*)d_in[15];  const float* bk3 = (const float*)d_in[16];
    const float* Wk4 = (const float*)d_in[17];  const float* bk4 = (const float*)d_in[18];
    const float* Wk5 = (const float*)d_in[19];  const float* bk5 = (const float*)d_in[20];

    int Bn = in_sizes[0] / (T_SEQ * I_IN);
    int smem_bytes = (KROWS * ROWS + 4 * ROWS * GSTR) * (int)sizeof(float);  // 152576 B

    cudaFuncSetAttribute(dfmnet_main, cudaFuncAttributeMaxDynamicSharedMemorySize, smem_bytes);

    prep_kernel<<<208, 256>>>(Wih1, Whh1, bih1, bhh1, Wih2, Whh2, bih2, bhh2);
    dfmnet_main<<<Bn / ROWS, NTHREADS, smem_bytes>>>(
        x, Wk0, bk0, Wk1, bk1, Wk2, bk2, Wk3, bk3, Wk4, bk4, Wk5, bk5,
        (float*)d_out, Bn);
}

// round 9
// speedup vs baseline: 1.0575x; 1.0575x over previous
#include <cuda_runtime.h>

// ---------------------------------------------------------------------------
// DFMNET: 2-layer LSTM (B=2048, T=256, I=64, H=128) + 6-layer MLP head.
// Persistent CTA per 16 batch rows runs all 256 timesteps.
// R9: R8's 8-cols x 8-rows thread mapping (best FMA:LDS ratio: 1 LDS.128 per
// 32 FFMA2) but at 256 threads / split-K 2 so the register budget is
// 255/thread -> no spills (R8 spilled at the 512-thread 128-reg cap).
// Weights fp32 [chunk][64 col-strips][16] -> 4 coalesced LDG.128 per chunk
// per thread, depth-1 double-buffered with padded tail.
// ---------------------------------------------------------------------------

#define T_SEQ    256
#define I_IN     64
#define H_HID    128
#define ROWS     16            // batch rows per CTA
#define NTHREADS 256
#define KROWS    320           // xh rows: [x(64) | h1(128) | h2(128)]
#define GSTR     516           // gate-buffer row stride (floats)
#define BSTR     (ROWS * GSTR) // per-partial-buffer stride (floats)

typedef unsigned long long ull;

// Weights: [chunk][cs=0..63][16 floats] where the 16 floats are
// (c0k0,c0k1, c1k0,c1k1, ..., c7k0,c7k1) for cols cs*8..cs*8+7, k=2c,2c+1.
// +1 zero-padded chunk so the depth-1 prefetch never branches.
__device__ __align__(16) float g_Wt1[(96 + 1) * 1024];    // K=192 -> 96 chunks
__device__ __align__(16) float g_Wt2[(128 + 1) * 1024];   // K=256 -> 128 chunks
__device__ float g_b1[512];
__device__ float g_b2[512];

// ---- packed fp32x2 helpers ----
__device__ __forceinline__ ull fma2(ull a, ull b, ull c) {
    ull d;
    asm("fma.rn.f32x2 %0, %1, %2, %3;" : "=l"(d) : "l"(a), "l"(b), "l"(c));
    return d;
}
__device__ __forceinline__ void unpack2(ull v, float& lo, float& hi) {
    unsigned a, b;
    asm("mov.b64 {%0, %1}, %2;" : "=r"(a), "=r"(b) : "l"(v));
    lo = __uint_as_float(a); hi = __uint_as_float(b);
}
__device__ __forceinline__ ull dup2(float w) {
    ull r; unsigned u = __float_as_uint(w);
    asm("mov.b64 %0, {%1, %1};" : "=l"(r) : "r"(u));
    return r;
}

__device__ __forceinline__ float sigf(float v) {
    return __fdividef(1.f, 1.f + __expf(-v));
}
__device__ __forceinline__ float tanhf_fast(float v) {
    float z = fminf(fmaxf(v, -15.f), 15.f);
    float e = __expf(-2.f * z);
    return __fdividef(1.f - e, 1.f + e);
}

// ---------------------------------------------------------------------------
// Weight repack into [chunk][cs][ci*2+s] layout described above.
// ---------------------------------------------------------------------------
__global__ void prep_kernel(const float* __restrict__ Wih1, const float* __restrict__ Whh1,
                            const float* __restrict__ bih1, const float* __restrict__ bhh1,
                            const float* __restrict__ Wih2, const float* __restrict__ Whh2,
                            const float* __restrict__ bih2, const float* __restrict__ bhh2)
{
    int tid = blockIdx.x * blockDim.x + threadIdx.x;
    int stride = gridDim.x * blockDim.x;
    if (tid < 512) {
        g_b1[tid] = bih1[tid] + bhh1[tid];
        g_b2[tid] = bih2[tid] + bhh2[tid];
    }
    for (int e = tid; e < 97 * 1024; e += stride) {
        int c = e >> 10, r = e & 1023;
        int cs = r >> 4, q = r & 15, ci = q >> 1, s = q & 1;
        int g = cs * 8 + ci;
        int k = 2 * c + s;
        float w = 0.f;
        if (k < 192) w = (k < 64) ? Wih1[g * 64 + k] : Whh1[g * 128 + (k - 64)];
        g_Wt1[e] = w;
    }
    for (int e = tid; e < 129 * 1024; e += stride) {
        int c = e >> 10, r = e & 1023;
        int cs = r >> 4, q = r & 15, ci = q >> 1, s = q & 1;
        int g = cs * 8 + ci;
        int k = 2 * c + s;
        float w = 0.f;
        if (k < 256) w = (k < 128) ? Wih2[g * 128 + k] : Whh2[g * 128 + (k - 128)];
        g_Wt2[e] = w;
    }
}

// ---------------------------------------------------------------------------
// Partial gate GEMM over chunk range [cb, cb+nc):
//   gbuf[16][GSTR] = (bias?) + xh-slice @ Wt-slice for this thread's
//   8 cols (cs*8..cs*8+7) x 8 rows (rg*8..rg*8+7).
// acc[ci][rp] = f32x2 over rows (rg*8+2rp, rg*8+2rp+1), col cs*8+ci.
// Per chunk/thread: 4 LDG.128 (prefetch, coalesced), 4 broadcast LDS.128,
// 16 dup MOVs (alu pipe), 64 FFMA2 (the binder).
// ---------------------------------------------------------------------------
__device__ __forceinline__ void gemm_gates(const float* __restrict__ Wt,
                                           const float* __restrict__ bias,
                                           const float* __restrict__ xh,   // [k][16]
                                           float* __restrict__ gbuf,       // [16][GSTR]
                                           int cb, int nc, int rg, int cs, bool add_bias)
{
    const int c0 = cs * 8;
    ull acc[8][4];
    if (add_bias) {
#pragma unroll
        for (int ci = 0; ci < 8; ci++) {
            ull b = dup2(bias[c0 + ci]);
#pragma unroll
            for (int rp = 0; rp < 4; rp++) acc[ci][rp] = b;
        }
    } else {
#pragma unroll
        for (int ci = 0; ci < 8; ci++)
#pragma unroll
            for (int rp = 0; rp < 4; rp++) acc[ci][rp] = 0ull;
    }

    const float4* Wp = (const float4*)(Wt + (cb * 64 + cs) * 16);  // 4 float4/thread/chunk
    float4 w0 = Wp[0], w1 = Wp[1], w2 = Wp[2], w3 = Wp[3];
    const ulonglong2* xq = (const ulonglong2*)(xh + cb * 32 + rg * 8);

#pragma unroll 4
    for (int c = 0; c < nc; c++) {
        // prefetch next chunk's weights (padded tail: always safe)
        float4 n0 = Wp[256], n1 = Wp[257], n2 = Wp[258], n3 = Wp[259];
        Wp += 256;
        // this thread's 8 rows for k=2c (q0,q1) and k=2c+1 (q2,q3); broadcast
        ulonglong2 q0 = xq[0], q1 = xq[1];
        ulonglong2 q2 = xq[4], q3 = xq[5];
        xq += 8;

        ull t;
        // ci=0
        t = dup2(w0.x);
        acc[0][0] = fma2(t, q0.x, acc[0][0]); acc[0][1] = fma2(t, q0.y, acc[0][1]);
        acc[0][2] = fma2(t, q1.x, acc[0][2]); acc[0][3] = fma2(t, q1.y, acc[0][3]);
        t = dup2(w0.y);
        acc[0][0] = fma2(t, q2.x, acc[0][0]); acc[0][1] = fma2(t, q2.y, acc[0][1]);
        acc[0][2] = fma2(t, q3.x, acc[0][2]); acc[0][3] = fma2(t, q3.y, acc[0][3]);
        // ci=1
        t = dup2(w0.z);
        acc[1][0] = fma2(t, q0.x, acc[1][0]); acc[1][1] = fma2(t, q0.y, acc[1][1]);
        acc[1][2] = fma2(t, q1.x, acc[1][2]); acc[1][3] = fma2(t, q1.y, acc[1][3]);
        t = dup2(w0.w);
        acc[1][0] = fma2(t, q2.x, acc[1][0]); acc[1][1] = fma2(t, q2.y, acc[1][1]);
        acc[1][2] = fma2(t, q3.x, acc[1][2]); acc[1][3] = fma2(t, q3.y, acc[1][3]);
        // ci=2
        t = dup2(w1.x);
        acc[2][0] = fma2(t, q0.x, acc[2][0]); acc[2][1] = fma2(t, q0.y, acc[2][1]);
        acc[2][2] = fma2(t, q1.x, acc[2][2]); acc[2][3] = fma2(t, q1.y, acc[2][3]);
        t = dup2(w1.y);
        acc[2][0] = fma2(t, q2.x, acc[2][0]); acc[2][1] = fma2(t, q2.y, acc[2][1]);
        acc[2][2] = fma2(t, q3.x, acc[2][2]); acc[2][3] = fma2(t, q3.y, acc[2][3]);
        // ci=3
        t = dup2(w1.z);
        acc[3][0] = fma2(t, q0.x, acc[3][0]); acc[3][1] = fma2(t, q0.y, acc[3][1]);
        acc[3][2] = fma2(t, q1.x, acc[3][2]); acc[3][3] = fma2(t, q1.y, acc[3][3]);
        t = dup2(w1.w);
        acc[3][0] = fma2(t, q2.x, acc[3][0]); acc[3][1] = fma2(t, q2.y, acc[3][1]);
        acc[3][2] = fma2(t, q3.x, acc[3][2]); acc[3][3] = fma2(t, q3.y, acc[3][3]);
        // ci=4
        t = dup2(w2.x);
        acc[4][0] = fma2(t, q0.x, acc[4][0]); acc[4][1] = fma2(t, q0.y, acc[4][1]);
        acc[4][2] = fma2(t, q1.x, acc[4][2]); acc[4][3] = fma2(t, q1.y, acc[4][3]);
        t = dup2(w2.y);
        acc[4][0] = fma2(t, q2.x, acc[4][0]); acc[4][1] = fma2(t, q2.y, acc[4][1]);
        acc[4][2] = fma2(t, q3.x, acc[4][2]); acc[4][3] = fma2(t, q3.y, acc[4][3]);
        // ci=5
        t = dup2(w2.z);
        acc[5][0] = fma2(t, q0.x, acc[5][0]); acc[5][1] = fma2(t, q0.y, acc[5][1]);
        acc[5][2] = fma2(t, q1.x, acc[5][2]); acc[5][3] = fma2(t, q1.y, acc[5][3]);
        t = dup2(w2.w);
        acc[5][0] = fma2(t, q2.x, acc[5][0]); acc[5][1] = fma2(t, q2.y, acc[5][1]);
        acc[5][2] = fma2(t, q3.x, acc[5][2]); acc[5][3] = fma2(t, q3.y, acc[5][3]);
        // ci=6
        t = dup2(w3.x);
        acc[6][0] = fma2(t, q0.x, acc[6][0]); acc[6][1] = fma2(t, q0.y, acc[6][1]);
        acc[6][2] = fma2(t, q1.x, acc[6][2]); acc[6][3] = fma2(t, q1.y, acc[6][3]);
        t = dup2(w3.y);
        acc[6][0] = fma2(t, q2.x, acc[6][0]); acc[6][1] = fma2(t, q2.y, acc[6][1]);
        acc[6][2] = fma2(t, q3.x, acc[6][2]); acc[6][3] = fma2(t, q3.y, acc[6][3]);
        // ci=7
        t = dup2(w3.z);
        acc[7][0] = fma2(t, q0.x, acc[7][0]); acc[7][1] = fma2(t, q0.y, acc[7][1]);
        acc[7][2] = fma2(t, q1.x, acc[7][2]); acc[7][3] = fma2(t, q1.y, acc[7][3]);
        t = dup2(w3.w);
        acc[7][0] = fma2(t, q2.x, acc[7][0]); acc[7][1] = fma2(t, q2.y, acc[7][1]);
        acc[7][2] = fma2(t, q3.x, acc[7][2]); acc[7][3] = fma2(t, q3.y, acc[7][3]);

        w0 = n0; w1 = n1; w2 = n2; w3 = n3;
    }

    // write 8 rows x 8 cols: two float4 STS per row
#pragma unroll
    for (int rp = 0; rp < 4; rp++) {
        float la[8], ha[8];
#pragma unroll
        for (int ci = 0; ci < 8; ci++) unpack2(acc[ci][rp], la[ci], ha[ci]);
        int row0 = rg * 8 + 2 * rp;
        float* d0 = gbuf + row0 * GSTR + c0;
        float* d1 = d0 + GSTR;
        *(float4*)(d0)     = make_float4(la[0], la[1], la[2], la[3]);
        *(float4*)(d0 + 4) = make_float4(la[4], la[5], la[6], la[7]);
        *(float4*)(d1)     = make_float4(ha[0], ha[1], ha[2], ha[3]);
        *(float4*)(d1 + 4) = make_float4(ha[4], ha[5], ha[6], ha[7]);
    }
}

// Small MLP layer over the CTA's 16 rows (head only; negligible cost)
__device__ __forceinline__ void mlp_layer(const float* __restrict__ vin, int Din,
                                          const float* __restrict__ W, const float* __restrict__ b,
                                          float* __restrict__ vout, int Dout, bool relu, int tid)
{
    for (int e = tid; e < ROWS * Dout; e += NTHREADS) {
        int r = e / Dout, o = e - r * Dout;
        const float* w = W + o * Din;
        const float* vi = vin + r * Din;
        float s = b[o];
        for (int i = 0; i < Din; i += 4) {
            s += w[i] * vi[i] + w[i + 1] * vi[i + 1] + w[i + 2] * vi[i + 2] + w[i + 3] * vi[i + 3];
        }
        vout[e] = relu ? fmaxf(s, 0.f) : s;
    }
    __syncthreads();
}

// ---------------------------------------------------------------------------
__global__ void __launch_bounds__(NTHREADS, 1)
dfmnet_main(const float* __restrict__ x,
            const float* __restrict__ Wk0, const float* __restrict__ bk0,
            const float* __restrict__ Wk1, const float* __restrict__ bk1,
            const float* __restrict__ Wk2, const float* __restrict__ bk2,
            const float* __restrict__ Wk3, const float* __restrict__ bk3,
            const float* __restrict__ Wk4, const float* __restrict__ bk4,
            const float* __restrict__ Wk5, const float* __restrict__ bk5,
            float* __restrict__ out, int Bn)
{
    extern __shared__ float sm[];
    float* xh    = sm;                    // [KROWS][16]
    float* gates = sm + KROWS * ROWS;     // 2 partial buffers [16][GSTR] each

    const int tid = threadIdx.x;
    const int kg  = tid >> 7;             // k-group 0/1 (4 warps each)
    const int rg  = (tid >> 6) & 1;       // row-group 0/1 (uniform per warp)
    const int cs  = tid & 63;             // col-strip: cols cs*8..cs*8+7
    const int b0  = blockIdx.x * ROWS;

    for (int e = tid; e < KROWS * ROWS; e += NTHREADS) xh[e] = 0.f;
    float c1r[8], c2r[8];
#pragma unroll
    for (int p = 0; p < 8; p++) { c1r[p] = 0.f; c2r[p] = 0.f; }
    __syncthreads();

    const float* xbase = x + (size_t)b0 * T_SEQ * I_IN;
    float* mybuf = gates + kg * BSTR;

    for (int t = 0; t < T_SEQ; t++) {
        // load x_t (16 rows x 64) transposed into xh rows [0,64)
#pragma unroll
        for (int q = 0; q < 4; q++) {
            int e = tid + q * NTHREADS;            // 0..1023
            int r = e >> 6, k = e & 63;
            xh[k * ROWS + r] = xbase[(size_t)r * (T_SEQ * I_IN) + t * I_IN + k];
        }
        __syncthreads();

        // layer 1: K=192 -> 96 chunks, 48 per k-group
        gemm_gates(g_Wt1, g_b1, xh, mybuf, kg * 48, 48, rg, cs, kg == 0);
        __syncthreads();

        // layer 1 activation: h1 -> xh rows [64,192); sum 2 partials
#pragma unroll
        for (int p = 0; p < 8; p++) {
            int idx = tid + p * NTHREADS;          // 0..2047
            int j = idx >> 4, r = idx & 15;
            const float* gb = gates + r * GSTR + j;
            float pi = gb[0]   + gb[BSTR];
            float pf = gb[128] + gb[BSTR + 128];
            float pg = gb[256] + gb[BSTR + 256];
            float po = gb[384] + gb[BSTR + 384];
            float iv = sigf(pi);
            float fv = sigf(pf);
            float gv = tanhf_fast(pg);
            float ov = sigf(po);
            float c = fv * c1r[p] + iv * gv;
            c1r[p] = c;
            xh[(64 + j) * ROWS + r] = ov * tanhf_fast(c);
        }
        __syncthreads();

        // layer 2: K=256 -> 128 chunks, 64 per k-group; xh rows [64,320)
        gemm_gates(g_Wt2, g_b2, xh + 64 * ROWS, mybuf, kg * 64, 64, rg, cs, kg == 0);
        __syncthreads();

        // layer 2 activation: h2 -> xh rows [192,320)
#pragma unroll
        for (int p = 0; p < 8; p++) {
            int idx = tid + p * NTHREADS;
            int j = idx >> 4, r = idx & 15;
            const float* gb = gates + r * GSTR + j;
            float pi = gb[0]   + gb[BSTR];
            float pf = gb[128] + gb[BSTR + 128];
            float pg = gb[256] + gb[BSTR + 256];
            float po = gb[384] + gb[BSTR + 384];
            float iv = sigf(pi);
            float fv = sigf(pf);
            float gv = tanhf_fast(pg);
            float ov = sigf(po);
            float c = fv * c2r[p] + iv * gv;
            c2r[p] = c;
            xh[(192 + j) * ROWS + r] = ov * tanhf_fast(c);
        }
        // next iter's x-load writes disjoint smem; its __syncthreads orders
        // these h2 writes (and this phase's gates reads) before reuse.
    }
    __syncthreads();

    // ---- outputs: tuple (y, h2, r) flattened ----
    float* out_y  = out;                              // [Bn][64]
    float* out_h2 = out + (size_t)Bn * 64;            // [Bn][128]
    float* out_r  = out + (size_t)Bn * 192;           // [Bn][192]

    float* va = gates;              // [16][192]
    float* vb = gates + ROWS * 192; // [16][128]
    float* vc = vb + ROWS * 128;    // [16][128]
    for (int e = tid; e < ROWS * 192; e += NTHREADS) {
        int r = e / 192, j = e - r * 192;
        float v = (j < 128) ? xh[(192 + j) * ROWS + r] : xh[(j - 128) * ROWS + r];
        va[e] = v;
        out_r[(size_t)(b0 + r) * 192 + j] = v;
        if (j < 128) out_h2[(size_t)(b0 + r) * 128 + j] = v;
    }
    __syncthreads();

    mlp_layer(va, 192, Wk0, bk0, vb, 128, true, tid);
    mlp_layer(vb, 128, Wk1, bk1, vc, 128, true, tid);
    mlp_layer(vc, 128, Wk2, bk2, vb, 128, true, tid);
    mlp_layer(vb, 128, Wk3, bk3, vc, 128, true, tid);
    mlp_layer(vc, 128, Wk4, bk4, vb, 128, true, tid);

    for (int e = tid; e < ROWS * 64; e += NTHREADS) {
        int r = e >> 6, o = e & 63;
        const float* w = Wk5 + o * 128;
        const float* vi = vb + r * 128;
        float s = bk5[o];
        for (int i = 0; i < 128; i += 4) {
            s += w[i] * vi[i] + w[i + 1] * vi[i + 1] + w[i + 2] * vi[i + 2] + w[i + 3] * vi[i + 3];
        }
        out_y[(size_t)(b0 + r) * 64 + o] = s;
    }
}

// ---------------------------------------------------------------------------
extern "C" void kernel_launch(void* const* d_in, const int* in_sizes, int n_in,
                              void* d_out, int out_size)
{
    const float* x    = (const float*)d_in[0];
    const float* Wih1 = (const float*)d_in[1];
    const float* Whh1 = (const float*)d_in[2];
    const float* bih1 = (const float*)d_in[3];
    const float* bhh1 = (const float*)d_in[4];
    const float* Wih2 = (const float*)d_in[5];
    const float* Whh2 = (const float*)d_in[6];
    const float* bih2 = (const float*)d_in[7];
    const float* bhh2 = (const float*)d_in[8];
    const float* Wk0 = (const float*)d_in[9];   const float* bk0 = (const float*)d_in[10];
    const float* Wk1 = (const float*)d_in[11];  const float* bk1 = (const float*)d_in[12];
    const float* Wk2 = (const float*)d_in[13];  const float* bk2 = (const float*)d_in[14];
    const float* Wk3 = (const float*)d_in[15];  const float* bk3 = (const float*)d_in[16];
    const float* Wk4 = (const float*)d_in[17];  const float* bk4 = (const float*)d_in[18];
    const float* Wk5 = (const float*)d_in[19];  const float* bk5 = (const float*)d_in[20];

    int Bn = in_sizes[0] / (T_SEQ * I_IN);
    int smem_bytes = (KROWS * ROWS + 2 * ROWS * GSTR) * (int)sizeof(float);  // 86528 B

    cudaFuncSetAttribute(dfmnet_main, cudaFuncAttributeMaxDynamicSharedMemorySize, smem_bytes);

    prep_kernel<<<208, 256>>>(Wih1, Whh1, bih1, bhh1, Wih2, Whh2, bih2, bhh2);
    dfmnet_main<<<Bn / ROWS, NTHREADS, smem_bytes>>>(
        x, Wk0, bk0, Wk1, bk1, Wk2, bk2, Wk3, bk3, Wk4, bk4, Wk5, bk5,
        (float*)d_out, Bn);
}

// round 10
// speedup vs baseline: 1.7309x; 1.6368x over previous
#include <cuda_runtime.h>

// ---------------------------------------------------------------------------
// DFMNET: 2-layer LSTM (B=2048, T=256, I=64, H=128) + 6-layer MLP head.
// Persistent CTA per 16 batch rows runs all 256 timesteps.
// R10: identical to R9 (8 cols x 8 rows / thread, 256 threads, split-K 2)
// EXCEPT the weight layout: [chunk][j][cs][float4] so every LDG.128 is
// warp-contiguous (4 lines / 4 wavefronts), vs R9's per-thread-contiguous
// layout whose 64B lane stride cost 16 lines per LDG.128 (L1 was 2.5x FMA).
// With the fix: ~21.5K L1 wavefronts vs 28.7K FMA cyc per step -> FMA binds.
// ---------------------------------------------------------------------------

#define T_SEQ    256
#define I_IN     64
#define H_HID    128
#define ROWS     16            // batch rows per CTA
#define NTHREADS 256
#define KROWS    320           // xh rows: [x(64) | h1(128) | h2(128)]
#define GSTR     516           // gate-buffer row stride (floats)
#define BSTR     (ROWS * GSTR) // per-partial-buffer stride (floats)

typedef unsigned long long ull;

// Weights: [chunk][j=0..3][cs=0..63][4 floats]. For thread strip cs, the
// concatenation over j of its 4 float4s gives (c0k0,c0k1,...,c7k0,c7k1) for
// cols cs*8..cs*8+7, k = 2c, 2c+1 (same per-thread semantics as R9).
// +1 zero-padded chunk so the depth-1 prefetch never branches.
__device__ __align__(16) float g_Wt1[(96 + 1) * 1024];    // K=192 -> 96 chunks
__device__ __align__(16) float g_Wt2[(128 + 1) * 1024];   // K=256 -> 128 chunks
__device__ float g_b1[512];
__device__ float g_b2[512];

// ---- packed fp32x2 helpers ----
__device__ __forceinline__ ull fma2(ull a, ull b, ull c) {
    ull d;
    asm("fma.rn.f32x2 %0, %1, %2, %3;" : "=l"(d) : "l"(a), "l"(b), "l"(c));
    return d;
}
__device__ __forceinline__ void unpack2(ull v, float& lo, float& hi) {
    unsigned a, b;
    asm("mov.b64 {%0, %1}, %2;" : "=r"(a), "=r"(b) : "l"(v));
    lo = __uint_as_float(a); hi = __uint_as_float(b);
}
__device__ __forceinline__ ull dup2(float w) {
    ull r; unsigned u = __float_as_uint(w);
    asm("mov.b64 %0, {%1, %1};" : "=l"(r) : "r"(u));
    return r;
}

__device__ __forceinline__ float sigf(float v) {
    return __fdividef(1.f, 1.f + __expf(-v));
}
__device__ __forceinline__ float tanhf_fast(float v) {
    float z = fminf(fmaxf(v, -15.f), 15.f);
    float e = __expf(-2.f * z);
    return __fdividef(1.f - e, 1.f + e);
}

// ---------------------------------------------------------------------------
// Weight repack into the coalesced [chunk][j][cs][f] layout.
//   e = c*1024 + j*256 + cs*4 + f ;  ci = j*2 + (f>>1), s = f&1
//   g = cs*8 + ci ; k = 2c + s
// ---------------------------------------------------------------------------
__global__ void prep_kernel(const float* __restrict__ Wih1, const float* __restrict__ Whh1,
                            const float* __restrict__ bih1, const float* __restrict__ bhh1,
                            const float* __restrict__ Wih2, const float* __restrict__ Whh2,
                            const float* __restrict__ bih2, const float* __restrict__ bhh2)
{
    int tid = blockIdx.x * blockDim.x + threadIdx.x;
    int stride = gridDim.x * blockDim.x;
    if (tid < 512) {
        g_b1[tid] = bih1[tid] + bhh1[tid];
        g_b2[tid] = bih2[tid] + bhh2[tid];
    }
    for (int e = tid; e < 97 * 1024; e += stride) {
        int c = e >> 10, r = e & 1023;
        int j = r >> 8, cs = (r >> 2) & 63, f = r & 3;
        int ci = j * 2 + (f >> 1), s = f & 1;
        int g = cs * 8 + ci;
        int k = 2 * c + s;
        float w = 0.f;
        if (k < 192) w = (k < 64) ? Wih1[g * 64 + k] : Whh1[g * 128 + (k - 64)];
        g_Wt1[e] = w;
    }
    for (int e = tid; e < 129 * 1024; e += stride) {
        int c = e >> 10, r = e & 1023;
        int j = r >> 8, cs = (r >> 2) & 63, f = r & 3;
        int ci = j * 2 + (f >> 1), s = f & 1;
        int g = cs * 8 + ci;
        int k = 2 * c + s;
        float w = 0.f;
        if (k < 256) w = (k < 128) ? Wih2[g * 128 + k] : Whh2[g * 128 + (k - 128)];
        g_Wt2[e] = w;
    }
}

// ---------------------------------------------------------------------------
// Partial gate GEMM over chunk range [cb, cb+nc):
//   gbuf[16][GSTR] = (bias?) + xh-slice @ Wt-slice for this thread's
//   8 cols (cs*8..cs*8+7) x 8 rows (rg*8..rg*8+7).
// acc[ci][rp] = f32x2 over rows (rg*8+2rp, rg*8+2rp+1), col cs*8+ci.
// Per chunk/thread: 4 COALESCED LDG.128 (4 wf each; prefetched depth-1),
// 4 broadcast LDS.128, 16 dup MOVs (alu pipe), 64 FFMA2 (the binder).
// ---------------------------------------------------------------------------
__device__ __forceinline__ void gemm_gates(const float* __restrict__ Wt,
                                           const float* __restrict__ bias,
                                           const float* __restrict__ xh,   // [k][16]
                                           float* __restrict__ gbuf,       // [16][GSTR]
                                           int cb, int nc, int rg, int cs, bool add_bias)
{
    const int c0 = cs * 8;
    ull acc[8][4];
    if (add_bias) {
#pragma unroll
        for (int ci = 0; ci < 8; ci++) {
            ull b = dup2(bias[c0 + ci]);
#pragma unroll
            for (int rp = 0; rp < 4; rp++) acc[ci][rp] = b;
        }
    } else {
#pragma unroll
        for (int ci = 0; ci < 8; ci++)
#pragma unroll
            for (int rp = 0; rp < 4; rp++) acc[ci][rp] = 0ull;
    }

    // coalesced: lane cs reads float4 at (chunk base) + j*64 float4s + cs
    const float4* Wp = (const float4*)Wt + cb * 256 + cs;
    float4 w0 = Wp[0], w1 = Wp[64], w2 = Wp[128], w3 = Wp[192];
    const ulonglong2* xq = (const ulonglong2*)(xh + cb * 32 + rg * 8);

#pragma unroll 4
    for (int c = 0; c < nc; c++) {
        // prefetch next chunk's weights (padded tail: always safe)
        float4 n0 = Wp[256], n1 = Wp[320], n2 = Wp[384], n3 = Wp[448];
        Wp += 256;
        // this thread's 8 rows for k=2c (q0,q1) and k=2c+1 (q2,q3); broadcast
        ulonglong2 q0 = xq[0], q1 = xq[1];
        ulonglong2 q2 = xq[4], q3 = xq[5];
        xq += 8;

        ull t;
        // ci=0
        t = dup2(w0.x);
        acc[0][0] = fma2(t, q0.x, acc[0][0]); acc[0][1] = fma2(t, q0.y, acc[0][1]);
        acc[0][2] = fma2(t, q1.x, acc[0][2]); acc[0][3] = fma2(t, q1.y, acc[0][3]);
        t = dup2(w0.y);
        acc[0][0] = fma2(t, q2.x, acc[0][0]); acc[0][1] = fma2(t, q2.y, acc[0][1]);
        acc[0][2] = fma2(t, q3.x, acc[0][2]); acc[0][3] = fma2(t, q3.y, acc[0][3]);
        // ci=1
        t = dup2(w0.z);
        acc[1][0] = fma2(t, q0.x, acc[1][0]); acc[1][1] = fma2(t, q0.y, acc[1][1]);
        acc[1][2] = fma2(t, q1.x, acc[1][2]); acc[1][3] = fma2(t, q1.y, acc[1][3]);
        t = dup2(w0.w);
        acc[1][0] = fma2(t, q2.x, acc[1][0]); acc[1][1] = fma2(t, q2.y, acc[1][1]);
        acc[1][2] = fma2(t, q3.x, acc[1][2]); acc[1][3] = fma2(t, q3.y, acc[1][3]);
        // ci=2
        t = dup2(w1.x);
        acc[2][0] = fma2(t, q0.x, acc[2][0]); acc[2][1] = fma2(t, q0.y, acc[2][1]);
        acc[2][2] = fma2(t, q1.x, acc[2][2]); acc[2][3] = fma2(t, q1.y, acc[2][3]);
        t = dup2(w1.y);
        acc[2][0] = fma2(t, q2.x, acc[2][0]); acc[2][1] = fma2(t, q2.y, acc[2][1]);
        acc[2][2] = fma2(t, q3.x, acc[2][2]); acc[2][3] = fma2(t, q3.y, acc[2][3]);
        // ci=3
        t = dup2(w1.z);
        acc[3][0] = fma2(t, q0.x, acc[3][0]); acc[3][1] = fma2(t, q0.y, acc[3][1]);
        acc[3][2] = fma2(t, q1.x, acc[3][2]); acc[3][3] = fma2(t, q1.y, acc[3][3]);
        t = dup2(w1.w);
        acc[3][0] = fma2(t, q2.x, acc[3][0]); acc[3][1] = fma2(t, q2.y, acc[3][1]);
        acc[3][2] = fma2(t, q3.x, acc[3][2]); acc[3][3] = fma2(t, q3.y, acc[3][3]);
        // ci=4
        t = dup2(w2.x);
        acc[4][0] = fma2(t, q0.x, acc[4][0]); acc[4][1] = fma2(t, q0.y, acc[4][1]);
        acc[4][2] = fma2(t, q1.x, acc[4][2]); acc[4][3] = fma2(t, q1.y, acc[4][3]);
        t = dup2(w2.y);
        acc[4][0] = fma2(t, q2.x, acc[4][0]); acc[4][1] = fma2(t, q2.y, acc[4][1]);
        acc[4][2] = fma2(t, q3.x, acc[4][2]); acc[4][3] = fma2(t, q3.y, acc[4][3]);
        // ci=5
        t = dup2(w2.z);
        acc[5][0] = fma2(t, q0.x, acc[5][0]); acc[5][1] = fma2(t, q0.y, acc[5][1]);
        acc[5][2] = fma2(t, q1.x, acc[5][2]); acc[5][3] = fma2(t, q1.y, acc[5][3]);
        t = dup2(w2.w);
        acc[5][0] = fma2(t, q2.x, acc[5][0]); acc[5][1] = fma2(t, q2.y, acc[5][1]);
        acc[5][2] = fma2(t, q3.x, acc[5][2]); acc[5][3] = fma2(t, q3.y, acc[5][3]);
        // ci=6
        t = dup2(w3.x);
        acc[6][0] = fma2(t, q0.x, acc[6][0]); acc[6][1] = fma2(t, q0.y, acc[6][1]);
        acc[6][2] = fma2(t, q1.x, acc[6][2]); acc[6][3] = fma2(t, q1.y, acc[6][3]);
        t = dup2(w3.y);
        acc[6][0] = fma2(t, q2.x, acc[6][0]); acc[6][1] = fma2(t, q2.y, acc[6][1]);
        acc[6][2] = fma2(t, q3.x, acc[6][2]); acc[6][3] = fma2(t, q3.y, acc[6][3]);
        // ci=7
        t = dup2(w3.z);
        acc[7][0] = fma2(t, q0.x, acc[7][0]); acc[7][1] = fma2(t, q0.y, acc[7][1]);
        acc[7][2] = fma2(t, q1.x, acc[7][2]); acc[7][3] = fma2(t, q1.y, acc[7][3]);
        t = dup2(w3.w);
        acc[7][0] = fma2(t, q2.x, acc[7][0]); acc[7][1] = fma2(t, q2.y, acc[7][1]);
        acc[7][2] = fma2(t, q3.x, acc[7][2]); acc[7][3] = fma2(t, q3.y, acc[7][3]);

        w0 = n0; w1 = n1; w2 = n2; w3 = n3;
    }

    // write 8 rows x 8 cols: two float4 STS per row
#pragma unroll
    for (int rp = 0; rp < 4; rp++) {
        float la[8], ha[8];
#pragma unroll
        for (int ci = 0; ci < 8; ci++) unpack2(acc[ci][rp], la[ci], ha[ci]);
        int row0 = rg * 8 + 2 * rp;
        float* d0 = gbuf + row0 * GSTR + c0;
        float* d1 = d0 + GSTR;
        *(float4*)(d0)     = make_float4(la[0], la[1], la[2], la[3]);
        *(float4*)(d0 + 4) = make_float4(la[4], la[5], la[6], la[7]);
        *(float4*)(d1)     = make_float4(ha[0], ha[1], ha[2], ha[3]);
        *(float4*)(d1 + 4) = make_float4(ha[4], ha[5], ha[6], ha[7]);
    }
}

// Small MLP layer over the CTA's 16 rows (head only; negligible cost)
__device__ __forceinline__ void mlp_layer(const float* __restrict__ vin, int Din,
                                          const float* __restrict__ W, const float* __restrict__ b,
                                          float* __restrict__ vout, int Dout, bool relu, int tid)
{
    for (int e = tid; e < ROWS * Dout; e += NTHREADS) {
        int r = e / Dout, o = e - r * Dout;
        const float* w = W + o * Din;
        const float* vi = vin + r * Din;
        float s = b[o];
        for (int i = 0; i < Din; i += 4) {
            s += w[i] * vi[i] + w[i + 1] * vi[i + 1] + w[i + 2] * vi[i + 2] + w[i + 3] * vi[i + 3];
        }
        vout[e] = relu ? fmaxf(s, 0.f) : s;
    }
    __syncthreads();
}

// ---------------------------------------------------------------------------
__global__ void __launch_bounds__(NTHREADS, 1)
dfmnet_main(const float* __restrict__ x,
            const float* __restrict__ Wk0, const float* __restrict__ bk0,
            const float* __restrict__ Wk1, const float* __restrict__ bk1,
            const float* __restrict__ Wk2, const float* __restrict__ bk2,
            const float* __restrict__ Wk3, const float* __restrict__ bk3,
            const float* __restrict__ Wk4, const float* __restrict__ bk4,
            const float* __restrict__ Wk5, const float* __restrict__ bk5,
            float* __restrict__ out, int Bn)
{
    extern __shared__ float sm[];
    float* xh    = sm;                    // [KROWS][16]
    float* gates = sm + KROWS * ROWS;     // 2 partial buffers [16][GSTR] each

    const int tid = threadIdx.x;
    const int kg  = tid >> 7;             // k-group 0/1 (4 warps each)
    const int rg  = (tid >> 6) & 1;       // row-group 0/1 (uniform per warp)
    const int cs  = tid & 63;             // col-strip: cols cs*8..cs*8+7
    const int b0  = blockIdx.x * ROWS;

    for (int e = tid; e < KROWS * ROWS; e += NTHREADS) xh[e] = 0.f;
    float c1r[8], c2r[8];
#pragma unroll
    for (int p = 0; p < 8; p++) { c1r[p] = 0.f; c2r[p] = 0.f; }
    __syncthreads();

    const float* xbase = x + (size_t)b0 * T_SEQ * I_IN;
    float* mybuf = gates + kg * BSTR;

    for (int t = 0; t < T_SEQ; t++) {
        // load x_t (16 rows x 64) transposed into xh rows [0,64)
#pragma unroll
        for (int q = 0; q < 4; q++) {
            int e = tid + q * NTHREADS;            // 0..1023
            int r = e >> 6, k = e & 63;
            xh[k * ROWS + r] = xbase[(size_t)r * (T_SEQ * I_IN) + t * I_IN + k];
        }
        __syncthreads();

        // layer 1: K=192 -> 96 chunks, 48 per k-group
        gemm_gates(g_Wt1, g_b1, xh, mybuf, kg * 48, 48, rg, cs, kg == 0);
        __syncthreads();

        // layer 1 activation: h1 -> xh rows [64,192); sum 2 partials
#pragma unroll
        for (int p = 0; p < 8; p++) {
            int idx = tid + p * NTHREADS;          // 0..2047
            int j = idx >> 4, r = idx & 15;
            const float* gb = gates + r * GSTR + j;
            float pi = gb[0]   + gb[BSTR];
            float pf = gb[128] + gb[BSTR + 128];
            float pg = gb[256] + gb[BSTR + 256];
            float po = gb[384] + gb[BSTR + 384];
            float iv = sigf(pi);
            float fv = sigf(pf);
            float gv = tanhf_fast(pg);
            float ov = sigf(po);
            float c = fv * c1r[p] + iv * gv;
            c1r[p] = c;
            xh[(64 + j) * ROWS + r] = ov * tanhf_fast(c);
        }
        __syncthreads();

        // layer 2: K=256 -> 128 chunks, 64 per k-group; xh rows [64,320)
        gemm_gates(g_Wt2, g_b2, xh + 64 * ROWS, mybuf, kg * 64, 64, rg, cs, kg == 0);
        __syncthreads();

        // layer 2 activation: h2 -> xh rows [192,320)
#pragma unroll
        for (int p = 0; p < 8; p++) {
            int idx = tid + p * NTHREADS;
            int j = idx >> 4, r = idx & 15;
            const float* gb = gates + r * GSTR + j;
            float pi = gb[0]   + gb[BSTR];
            float pf = gb[128] + gb[BSTR + 128];
            float pg = gb[256] + gb[BSTR + 256];
            float po = gb[384] + gb[BSTR + 384];
            float iv = sigf(pi);
            float fv = sigf(pf);
            float gv = tanhf_fast(pg);
            float ov = sigf(po);
            float c = fv * c2r[p] + iv * gv;
            c2r[p] = c;
            xh[(192 + j) * ROWS + r] = ov * tanhf_fast(c);
        }
        // next iter's x-load writes disjoint smem; its __syncthreads orders
        // these h2 writes (and this phase's gates reads) before reuse.
    }
    __syncthreads();

    // ---- outputs: tuple (y, h2, r) flattened ----
    float* out_y  = out;                              // [Bn][64]
    float* out_h2 = out + (size_t)Bn * 64;            // [Bn][128]
    float* out_r  = out + (size_t)Bn * 192;           // [Bn][192]

    float* va = gates;              // [16][192]
    float* vb = gates + ROWS * 192; // [16][128]
    float* vc = vb + ROWS * 128;    // [16][128]
    for (int e = tid; e < ROWS * 192; e += NTHREADS) {
        int r = e / 192, j = e - r * 192;
        float v = (j < 128) ? xh[(192 + j) * ROWS + r] : xh[(j - 128) * ROWS + r];
        va[e] = v;
        out_r[(size_t)(b0 + r) * 192 + j] = v;
        if (j < 128) out_h2[(size_t)(b0 + r) * 128 + j] = v;
    }
    __syncthreads();

    mlp_layer(va, 192, Wk0, bk0, vb, 128, true, tid);
    mlp_layer(vb, 128, Wk1, bk1, vc, 128, true, tid);
    mlp_layer(vc, 128, Wk2, bk2, vb, 128, true, tid);
    mlp_layer(vb, 128, Wk3, bk3, vc, 128, true, tid);
    mlp_layer(vc, 128, Wk4, bk4, vb, 128, true, tid);

    for (int e = tid; e < ROWS * 64; e += NTHREADS) {
        int r = e >> 6, o = e & 63;
        const float* w = Wk5 + o * 128;
        const float* vi = vb + r * 128;
        float s = bk5[o];
        for (int i = 0; i < 128; i += 4) {
            s += w[i] * vi[i] + w[i + 1] * vi[i + 1] + w[i + 2] * vi[i + 2] + w[i + 3] * vi[i + 3];
        }
        out_y[(size_t)(b0 + r) * 64 + o] = s;
    }
}

// ---------------------------------------------------------------------------
extern "C" void kernel_launch(void* const* d_in, const int* in_sizes, int n_in,
                              void* d_out, int out_size)
{
    const float* x    = (const float*)d_in[0];
    const float* Wih1 = (const float*)d_in[1];
    const float* Whh1 = (const float*)d_in[2];
    const float* bih1 = (const float*)d_in[3];
    const float* bhh1 = (const float*)d_in[4];
    const float* Wih2 = (const float*)d_in[5];
    const float* Whh2 = (const float*)d_in[6];
    const float* bih2 = (const float*)d_in[7];
    const float* bhh2 = (const float*)d_in[8];
    const float* Wk0 = (const float*)d_in[9];   const float* bk0 = (const float*)d_in[10];
    const float* Wk1 = (const float*)d_in[11];  const float* bk1 = (const float*)d_in[12];
    const float* Wk2 = (const float*)d_in[13];  const float* bk2 = (const float*)d_in[14];
    const float* Wk3 = (const float*)d_in[15];  const float* bk3 = (const float*)d_in[16];
    const float* Wk4 = (const float*)d_in[17];  const float* bk4 = (const float*)d_in[18];
    const float* Wk5 = (const float*)d_in[19];  const float* bk5 = (const float*)d_in[20];

    int Bn = in_sizes[0] / (T_SEQ * I_IN);
    int smem_bytes = (KROWS * ROWS + 2 * ROWS * GSTR) * (int)sizeof(float);  // 86528 B

    cudaFuncSetAttribute(dfmnet_main, cudaFuncAttributeMaxDynamicSharedMemorySize, smem_bytes);

    prep_kernel<<<208, 256>>>(Wih1, Whh1, bih1, bhh1, Wih2, Whh2, bih2, bhh2);
    dfmnet_main<<<Bn / ROWS, NTHREADS, smem_bytes>>>(
        x, Wk0, bk0, Wk1, bk1, Wk2, bk2, Wk3, bk3, Wk4, bk4, Wk5, bk5,
        (float*)d_out, Bn);
}